// round 10
// baseline (speedup 1.0000x reference)
#include <cuda_runtime.h>

#define NFFT 640
#define HOP  320
#define NF   321            // freq bins
#define NT   301            // time frames
#define TLEN 96000
#define NCHF 17             // 16 x-channels + ref(b=0)
#define NFRF (NCHF*NT)      // 5117 forward frames
#define MINV (7*NT)         // 2107 inverse frames
#define LPAD 96640
#define FT   (NF*NT)        // 96621
#define OFF_FEATS 768000

#define TWO_PI 6.283185307179586f

// table segment offsets inside k_tab's index space
#define TAB_CT   0                       // 12800  (32*20*20)
#define TAB_W32  12800                   // 544
#define TAB_TA   13344                   // 10880  (20*17*32)
#define TAB_TB   24224                   // 400    (transposed [n2][r])
#define TAB_WIN  24624                   // 640
#define TAB_INVW 25264                   // LPAD
#define TAB_END  (TAB_INVW + LPAD)

// ---------------- scratch (device globals; no allocation allowed) -------------
__device__ float  g_win[NFFT];
__device__ float  g_invw[LPAD];
__device__ float2 g_ct[32*20*20];      // fwd stage1 twiddle: [n1][n2][r] = (cos,-sin)(2pi r n/640)
__device__ float2 g_W32[32*17];        // fwd stage2 twiddle: [n1][q] = (cos,-sin)(2pi q n1/32)
__device__ float2 g_TA[20*17*32];      // inv stageA: [r][q][n1] = ck*(cos,+sin)(2pi k n1/640), k=20q+r (0 if k>320)
__device__ float2 g_TBt[20*20];        // inv stageB TRANSPOSED: [n2][r] = (cos,+sin)(2pi r n2/20)
__device__ float  g_framesT[NFFT*NFRF];// transposed windowed frames [n][m]
__device__ float2 g_Z[640*NFRF];       // fwd stage1 output, [(r*32+n1)][m]
__device__ float2 g_S[NF*NFRF];        // STFT, freq-major [f][m], m = ch*NT + t
__device__ float2 g_rp[323*309];       // padded refS (b=0)
__device__ float2 g_estF[NF*MINV];     // est freq-major [k][R], R = m*NT + t
__device__ float2 g_A1[640*MINV];      // inv stageA output, [(r*32+n1)][R]
__device__ float  g_y[MINV*NFFT];      // inverse frames (pre-OLA, windowed)

__device__ __forceinline__ float hannf(int n) {
    return 0.5f - 0.5f*cosf(TWO_PI * (float)n / (float)NFFT);
}

// ---------------- init: all twiddle tables + window + invw (one launch) -------
__global__ void k_tab() {
    int idx = blockIdx.x*blockDim.x + threadIdx.x;
    if (idx < TAB_W32) {
        // fwd stage1: pure twiddle
        int n1 = idx / 400;
        int rem = idx - n1*400;
        int n2 = rem / 20;
        int r  = rem - n2*20;
        int n = n1 + 32*n2;
        float s, c;
        sincosf(TWO_PI * (float)((r*n) % NFFT) / (float)NFFT, &s, &c);
        g_ct[idx] = make_float2(c, -s);
    } else if (idx < TAB_TA) {
        int e = idx - TAB_W32;
        int n1 = e / 17, q = e - n1*17;
        float s, c;
        sincosf(TWO_PI * (float)((q*n1) % 32) / 32.0f, &s, &c);
        g_W32[e] = make_float2(c, -s);
    } else if (idx < TAB_TB) {
        // inv stageA: ck * e^{+2pi i k n1/640}, k = 20q+r
        int e = idx - TAB_TA;
        int r = e / 544;
        int rem = e - r*544;
        int q = rem / 32, n1 = rem - q*32;
        int k = 20*q + r;
        float2 v = make_float2(0.f, 0.f);
        if (k <= 320) {
            float ck = (k == 0 || k == 320) ? 1.0f : 2.0f;
            float s, c;
            sincosf(TWO_PI * (float)((k*n1) % NFFT) / (float)NFFT, &s, &c);
            v = make_float2(ck*c, ck*s);
        }
        g_TA[e] = v;
    } else if (idx < TAB_WIN) {
        // inv stageB transposed: [n2][r] = e^{+2pi i r n2/20}
        int e = idx - TAB_TB;
        int n2 = e / 20, r = e - n2*20;
        float s, c;
        sincosf(TWO_PI * (float)((r*n2) % 20) / 20.0f, &s, &c);
        g_TBt[e] = make_float2(c, s);
    } else if (idx < TAB_INVW) {
        int n = idx - TAB_WIN;
        g_win[n] = hannf(n);
    } else if (idx < TAB_END) {
        // closed-form inverse window sum (periodic interior, short edges)
        int sp = idx - TAB_INVW;
        float wsum;
        if (sp < HOP) {
            float w = hannf(sp);
            wsum = w*w;
        } else if (sp < 96320) {
            int n1 = sp % HOP;
            float w0 = hannf(n1), w1 = hannf(n1 + HOP);
            wsum = w0*w0 + w1*w1;
        } else {
            float w = hannf(sp - 96000);
            wsum = w*w;
        }
        g_invw[sp] = (wsum > 1e-11f) ? (1.0f/wsum) : 1.0f;
    }
}

// ---------------- framing (windowed, transposed output [n][m]) ----------------
__global__ void k_framesT(const float* __restrict__ x, const float* __restrict__ ref) {
    __shared__ float s[32][33];
    int tx = threadIdx.x, ty = threadIdx.y;   // block (32,8)
    int m0 = blockIdx.x * 32;
    int n0 = blockIdx.y * 32;
    int n = n0 + tx;
    float w = g_win[n];
    #pragma unroll
    for (int r4 = 0; r4 < 4; r4++) {
        int mr = ty + r4*8;
        int m = m0 + mr;
        float v = 0.0f;
        if (m < NFRF) {
            int ch = m / NT;
            int t  = m - ch*NT;
            const float* sig = (ch < 16) ? (x + ch*TLEN) : ref;
            int p = t*HOP + n - HOP;
            if (p >= 0 && p < TLEN) v = sig[p];
        }
        s[mr][tx] = v * w;
    }
    __syncthreads();
    int m = m0 + tx;
    if (m < NFRF) {
        #pragma unroll
        for (int r4 = 0; r4 < 4; r4++) {
            int nr = ty + r4*8;
            g_framesT[(n0 + nr)*NFRF + m] = s[tx][nr];
        }
    }
}

// ---------------- fwd stage 1: Z[n1][r][m] = sum_n2 frames[m][n1+32n2]*ct[n1][n2][r]
// M-tile 256, 1 m/thread; twiddle reads vectorized LDS.128 (r-pairs)
__global__ void __launch_bounds__(256) k_stage1() {
    __shared__ float  As[20][256];
    __shared__ float4 cts4[200];           // = cts[400] float2, pairs of r
    int m0 = blockIdx.x * 256;
    int n1 = blockIdx.y;
    int lid = threadIdx.x;

    #pragma unroll
    for (int i = 0; i < 20; i++) {
        int e = i*256 + lid;
        int n2 = e >> 8, ml = e & 255;
        int m = m0 + ml;
        As[n2][ml] = (m < NFRF) ? g_framesT[(n1 + 32*n2)*NFRF + m] : 0.0f;
    }
    if (lid < 200) cts4[lid] = ((const float4*)g_ct)[n1*200 + lid];
    __syncthreads();

    float2 acc[20];
    #pragma unroll
    for (int r = 0; r < 20; r++) acc[r] = make_float2(0.f, 0.f);

    #pragma unroll
    for (int n2 = 0; n2 < 20; n2++) {
        float a = As[n2][lid];
        #pragma unroll
        for (int j = 0; j < 10; j++) {
            float4 c = cts4[n2*10 + j];
            acc[2*j  ].x += a*c.x;  acc[2*j  ].y += a*c.y;
            acc[2*j+1].x += a*c.z;  acc[2*j+1].y += a*c.w;
        }
    }

    int m = m0 + lid;
    if (m < NFRF) {
        #pragma unroll
        for (int r = 0; r < 20; r++)
            g_Z[(r*32 + n1)*NFRF + m] = acc[r];
    }
}

// ---------------- fwd stage 2: S[r+20q][m] = sum_n1 Z[n1][r][m] * W32[n1][q]
// Bs padded to 18/row for aligned float4 q-pair reads
__global__ void __launch_bounds__(256) k_stage2() {
    __shared__ float2 Zs[16][256];
    __shared__ float2 Bs2[32*18];
    int m0 = blockIdx.x * 256;
    int r  = blockIdx.y;
    int lid = threadIdx.x;
    const float4* Bs4 = (const float4*)Bs2;

    #pragma unroll
    for (int e = lid; e < 32*17; e += 256) {
        int n1 = e / 17, q = e - n1*17;
        Bs2[n1*18 + q] = g_W32[e];
    }

    float2 acc[17];
    #pragma unroll
    for (int q = 0; q < 17; q++) acc[q] = make_float2(0.f, 0.f);

    #pragma unroll
    for (int kh = 0; kh < 2; kh++) {
        __syncthreads();
        #pragma unroll
        for (int i = 0; i < 16; i++) {
            int e = i*256 + lid;
            int k = e >> 8, ml = e & 255;
            int m = m0 + ml;
            Zs[k][ml] = (m < NFRF) ? g_Z[(r*32 + kh*16 + k)*NFRF + m]
                                   : make_float2(0.f, 0.f);
        }
        __syncthreads();
        #pragma unroll
        for (int k = 0; k < 16; k++) {
            float2 a = Zs[k][lid];
            int kg = kh*16 + k;
            #pragma unroll
            for (int j = 0; j < 8; j++) {
                float4 b = Bs4[kg*9 + j];
                acc[2*j  ].x += a.x*b.x - a.y*b.y;
                acc[2*j  ].y += a.x*b.y + a.y*b.x;
                acc[2*j+1].x += a.x*b.z - a.y*b.w;
                acc[2*j+1].y += a.x*b.w + a.y*b.z;
            }
            float2 b16 = Bs2[kg*18 + 16];
            acc[16].x += a.x*b16.x - a.y*b16.y;
            acc[16].y += a.x*b16.y + a.y*b16.x;
        }
    }

    int m = m0 + lid;
    if (m < NFRF) {
        #pragma unroll
        for (int q = 0; q < 17; q++) {
            int f = r + 20*q;
            if (f < NF) g_S[f*NFRF + m] = acc[q];
        }
    }
}

// ---------------- covariance features ----------------
__global__ void k_cov(float* __restrict__ out) {
    int idx = blockIdx.x*blockDim.x + threadIdx.x;
    if (idx >= 2*FT) return;
    int t = idx % NT;
    int f = (idx / NT) % NF;
    int b = idx / FT;
    float2 S[8];
    #pragma unroll
    for (int c = 0; c < 8; c++)
        S[c] = g_S[f*NFRF + (b*8 + c)*NT + t];
    float* o = out + OFF_FEATS + (b*74)*FT + f*NT + t;
    int p = 0;
    #pragma unroll
    for (int i = 0; i < 8; i++) {
        #pragma unroll
        for (int j = i; j < 8; j++) {
            float re = S[i].x*S[j].x + S[i].y*S[j].y;   // S_i * conj(S_j)
            float im = S[i].y*S[j].x - S[i].x*S[j].y;
            o[(2*p    )*FT] = re;
            o[(2*p + 1)*FT] = im;
            p++;
        }
    }
    o[72*FT] = S[3].x;
    o[73*FT] = S[3].y;
}

// ---------------- padded refS (b=0) ----------------
__global__ void k_refpad() {
    int idx = blockIdx.x*blockDim.x + threadIdx.x;
    if (idx >= 323*309) return;
    int fp = idx / 309, tp = idx - fp*309;
    int f = fp - 1, t = tp - 4;
    float2 v = make_float2(0.f, 0.f);
    if (f >= 0 && f < NF && t >= 0 && t < NT)
        v = g_S[f*NFRF + 16*NT + t];
    g_rp[idx] = v;
}

// ---------------- deep filtering (b=0 only), freq-major output ----------------
__global__ void k_deepfilter(const float2* __restrict__ rtf) {
    int idx = blockIdx.x*blockDim.x + threadIdx.x;
    if (idx >= 7*FT) return;
    int t = idx % NT;
    int f = (idx / NT) % NF;
    int m = idx / FT;
    const float2* rbase = rtf + m*27*FT + f*NT + t;  // b=0: [m][27][F][T] float2
    float2 acc = make_float2(0.f, 0.f);
    #pragma unroll
    for (int ki = 0; ki < 3; ki++) {
        #pragma unroll
        for (int kj = 0; kj < 9; kj++) {
            float2 r = rbase[(ki*9 + kj)*FT];
            float2 p = g_rp[(f + ki)*309 + (t + kj)];
            acc.x += r.x*p.x - r.y*p.y;
            acc.y += r.x*p.y + r.y*p.x;
        }
    }
    g_estF[f*MINV + m*NT + t] = acc;   // [k][R], R = m*NT + t
}

// ---------------- inv stage A: A1[r][n1][R] = sum_q ck*E[20q+r][R]*e^{+2pi i k n1/640}
// block 256 = 2 groups of 128; group g computes n1 in [16g, 16g+16)
__global__ void __launch_bounds__(256) k_istageA() {
    __shared__ float2 Es[17][128];
    __shared__ float2 TAs[17*32];
    int m0 = blockIdx.x * 128;
    int r  = blockIdx.y;
    int tid = threadIdx.x;
    int lid = tid & 127;
    int grp = tid >> 7;
    const float4* TAs4 = (const float4*)TAs;

    for (int e = tid; e < 544; e += 256) TAs[e] = g_TA[r*544 + e];
    for (int e = tid; e < 17*128; e += 256) {
        int q = e >> 7, ml = e & 127;
        int k = 20*q + r;
        int Rm = m0 + ml;
        Es[q][ml] = (k < NF && Rm < MINV) ? g_estF[k*MINV + Rm] : make_float2(0.f, 0.f);
    }
    __syncthreads();

    float2 acc[16];
    #pragma unroll
    for (int j = 0; j < 16; j++) acc[j] = make_float2(0.f, 0.f);

    #pragma unroll
    for (int q = 0; q < 17; q++) {
        float2 a = Es[q][lid];
        #pragma unroll
        for (int j = 0; j < 8; j++) {
            float4 t = TAs4[q*16 + grp*8 + j];
            acc[2*j  ].x += a.x*t.x - a.y*t.y;
            acc[2*j  ].y += a.x*t.y + a.y*t.x;
            acc[2*j+1].x += a.x*t.z - a.y*t.w;
            acc[2*j+1].y += a.x*t.w + a.y*t.z;
        }
    }

    int R = m0 + lid;
    int n1b = grp*16;
    if (R < MINV) {
        #pragma unroll
        for (int j = 0; j < 16; j++)
            g_A1[(r*32 + n1b + j)*MINV + R] = acc[j];
    }
}

// ---------------- inv stage B: y[R][n] = win[n]/640 * Re(sum_r A1[r][n1][R]*e^{+2pi i r n2/20})
__global__ void __launch_bounds__(256) k_istageB() {
    __shared__ float2 A1s[20][8][33];    // [r][mloc][n1] (pad to 33 for conflict-free)
    __shared__ float2 TBs[400];          // transposed [n2][r]
    __shared__ float  wins[NFFT];
    int R0 = blockIdx.x * 8;
    int lid = threadIdx.x;
    const float4* TBs4 = (const float4*)TBs;

    #pragma unroll
    for (int e = lid; e < 400; e += 256) TBs[e] = g_TBt[e];
    #pragma unroll
    for (int e = lid; e < NFFT; e += 256) wins[e] = g_win[e] * (1.0f/640.0f);
    #pragma unroll
    for (int i = 0; i < 20; i++) {
        int e = i*256 + lid;
        int rn1 = e >> 3, mloc = e & 7;
        int r = rn1 >> 5, n1 = rn1 & 31;
        int R = R0 + mloc;
        A1s[r][mloc][n1] = (R < MINV) ? g_A1[rn1*MINV + R] : make_float2(0.f, 0.f);
    }
    __syncthreads();

    #pragma unroll
    for (int mloc = 0; mloc < 8; mloc++) {
        int R = R0 + mloc;
        if (R >= MINV) break;    // uniform across block
        #pragma unroll
        for (int nb = 0; nb < 3; nb++) {
            int n = nb*256 + lid;
            if (n < NFFT) {
                int n1 = n & 31, n2 = n >> 5;
                float acc = 0.0f;
                #pragma unroll
                for (int jr = 0; jr < 10; jr++) {       // r = 2jr, 2jr+1
                    float4 t = TBs4[n2*10 + jr];
                    float2 a0 = A1s[2*jr  ][mloc][n1];
                    float2 a1 = A1s[2*jr+1][mloc][n1];
                    acc += a0.x*t.x - a0.y*t.y;
                    acc += a1.x*t.z - a1.y*t.w;
                }
                g_y[R*NFFT + n] = acc * wins[n];
            }
        }
    }
}

// ---------------- overlap-add + interleave output ----------------
__global__ void k_ola(const float* __restrict__ ref, float* __restrict__ out) {
    int s = blockIdx.x*blockDim.x + threadIdx.x;
    if (s >= TLEN) return;
    int sp = s + HOP;                 // position in uncropped signal
    int t1 = sp / HOP;                // in [1, 300]
    int n1 = sp - t1*HOP;             // [0, 320)
    int t0 = t1 - 1;
    int nn0 = n1 + HOP;               // [320, 640)
    float iw = g_invw[sp];
    float* o = out + s*8;
    #pragma unroll
    for (int m = 0; m < 7; m++) {
        float v = (g_y[(m*NT + t0)*NFFT + nn0] + g_y[(m*NT + t1)*NFFT + n1]) * iw;
        o[m < 3 ? m : m + 1] = v;
    }
    o[3] = ref[s];
}

// ---------------- launch ----------------
extern "C" void kernel_launch(void* const* d_in, const int* in_sizes, int n_in,
                              void* d_out, int out_size) {
    const float*  x   = (const float*)d_in[0];
    const float2* rtf = (const float2*)d_in[1];  // [B][7][3][9][F][T][2]; b=0 slice
    const float*  ref = (const float*)d_in[2];   // [2][1][T]; b=0 slice
    float* out = (float*)d_out;

    k_tab<<<(TAB_END + 255)/256, 256>>>();
    {
        dim3 g((NFRF + 31)/32, NFFT/32);
        k_framesT<<<g, dim3(32, 8)>>>(x, ref);
    }
    {
        dim3 g((NFRF + 255)/256, 32);
        k_stage1<<<g, 256>>>();
    }
    {
        dim3 g((NFRF + 255)/256, 20);
        k_stage2<<<g, 256>>>();
    }
    k_cov<<<(2*FT + 255)/256, 256>>>(out);
    k_refpad<<<(323*309 + 255)/256, 256>>>();
    k_deepfilter<<<(7*FT + 255)/256, 256>>>(rtf);
    {
        dim3 g((MINV + 127)/128, 20);
        k_istageA<<<g, 256>>>();
    }
    {
        dim3 g((MINV + 7)/8);
        k_istageB<<<g, 256>>>();
    }
    k_ola<<<(TLEN + 255)/256, 256>>>(ref, out);
}

// round 12
// speedup vs baseline: 1.1122x; 1.1122x over previous
#include <cuda_runtime.h>

#define NFFT 640
#define HOP  320
#define NF   321            // freq bins
#define NT   301            // time frames
#define TLEN 96000
#define NCHF 17             // 16 x-channels + ref(b=0)
#define NFRF (NCHF*NT)      // 5117 forward frames
#define MINV (7*NT)         // 2107 inverse frames
#define LPAD 96640
#define FT   (NF*NT)        // 96621
#define OFF_FEATS 768000

#define TWO_PI 6.283185307179586f

// table segment offsets inside k_tab's index space
#define TAB_CT1  0                       // 6400  (32*10*20) fwd stage1, n2<10
#define TAB_W32E 6400                    // 160   (16*10) even-q twiddles (9 valid + pad)
#define TAB_W32O 6560                    // 128   (16*8)  odd-q twiddles
#define TAB_TA   6688                    // 10880 (20*17*32)
#define TAB_TB   17568                   // 400   (transposed [n2][r])
#define TAB_WIN  17968                   // 640
#define TAB_INVW 18608                   // LPAD
#define TAB_END  (TAB_INVW + LPAD)

// ---------------- scratch (device globals; no allocation allowed) -------------
__device__ float  g_win[NFFT];
__device__ float  g_invw[LPAD];
__device__ float2 g_ct1[32*10*20];     // fwd stage1: [n1][n2<10][r] = (cos,-sin)(2pi r (n1+32n2)/640)
__device__ float2 g_W32e[16*10];       // fwd stage2 even q: [n1][je] = e^{-2pi i (2je) n1/32}, je<9 valid
__device__ float2 g_W32o[16*8];        // fwd stage2 odd  q: [n1][jo] = e^{-2pi i (2jo+1) n1/32}
__device__ float2 g_TA[20*17*32];      // inv stageA: [r][q][n1] = ck*(cos,+sin)(2pi k n1/640), k=20q+r (0 if k>320)
__device__ float2 g_TBt[20*20];        // inv stageB TRANSPOSED: [n2][r] = (cos,+sin)(2pi r n2/20)
__device__ float  g_framesT[NFFT*NFRF];// transposed windowed frames [n][m]
__device__ float2 g_Z[640*NFRF];       // fwd stage1 output, [(r*32+n1)][m]
__device__ float2 g_S[NF*NFRF];        // STFT, freq-major [f][m], m = ch*NT + t
__device__ float2 g_rp[323*309];       // padded refS (b=0)
__device__ float2 g_estF[NF*MINV];     // est freq-major [k][R], R = m*NT + t
__device__ float2 g_A1[640*MINV];      // inv stageA output, [(r*32+n1)][R]
__device__ float  g_y[MINV*NFFT];      // inverse frames (pre-OLA, windowed)

__device__ __forceinline__ float hannf(int n) {
    return 0.5f - 0.5f*cosf(TWO_PI * (float)n / (float)NFFT);
}

// ---------------- init: all twiddle tables + window + invw (one launch) -------
__global__ void k_tab() {
    int idx = blockIdx.x*blockDim.x + threadIdx.x;
    if (idx < TAB_W32E) {
        // fwd stage1 (radix-2 over n2): only n2 in [0,10)
        int n1 = idx / 200;
        int rem = idx - n1*200;
        int n2 = rem / 20;
        int r  = rem - n2*20;
        int n = n1 + 32*n2;
        float s, c;
        sincosf(TWO_PI * (float)((r*n) % NFFT) / (float)NFFT, &s, &c);
        g_ct1[idx] = make_float2(c, -s);
    } else if (idx < TAB_W32O) {
        int e = idx - TAB_W32E;
        int n1 = e / 10, je = e - n1*10;
        float2 v = make_float2(0.f, 0.f);
        if (je < 9) {
            int q = 2*je;
            float s, c;
            sincosf(TWO_PI * (float)((q*n1) % 32) / 32.0f, &s, &c);
            v = make_float2(c, -s);
        }
        g_W32e[e] = v;
    } else if (idx < TAB_TA) {
        int e = idx - TAB_W32O;
        int n1 = e / 8, jo = e - n1*8;
        int q = 2*jo + 1;
        float s, c;
        sincosf(TWO_PI * (float)((q*n1) % 32) / 32.0f, &s, &c);
        g_W32o[e] = make_float2(c, -s);
    } else if (idx < TAB_TB) {
        // inv stageA: ck * e^{+2pi i k n1/640}, k = 20q+r
        int e = idx - TAB_TA;
        int r = e / 544;
        int rem = e - r*544;
        int q = rem / 32, n1 = rem - q*32;
        int k = 20*q + r;
        float2 v = make_float2(0.f, 0.f);
        if (k <= 320) {
            float ck = (k == 0 || k == 320) ? 1.0f : 2.0f;
            float s, c;
            sincosf(TWO_PI * (float)((k*n1) % NFFT) / (float)NFFT, &s, &c);
            v = make_float2(ck*c, ck*s);
        }
        g_TA[e] = v;
    } else if (idx < TAB_WIN) {
        // inv stageB transposed: [n2][r] = e^{+2pi i r n2/20}
        int e = idx - TAB_TB;
        int n2 = e / 20, r = e - n2*20;
        float s, c;
        sincosf(TWO_PI * (float)((r*n2) % 20) / 20.0f, &s, &c);
        g_TBt[e] = make_float2(c, s);
    } else if (idx < TAB_INVW) {
        int n = idx - TAB_WIN;
        g_win[n] = hannf(n);
    } else if (idx < TAB_END) {
        // closed-form inverse window sum (periodic interior, short edges)
        int sp = idx - TAB_INVW;
        float wsum;
        if (sp < HOP) {
            float w = hannf(sp);
            wsum = w*w;
        } else if (sp < 96320) {
            int n1 = sp % HOP;
            float w0 = hannf(n1), w1 = hannf(n1 + HOP);
            wsum = w0*w0 + w1*w1;
        } else {
            float w = hannf(sp - 96000);
            wsum = w*w;
        }
        g_invw[sp] = (wsum > 1e-11f) ? (1.0f/wsum) : 1.0f;
    }
}

// ---------------- framing (windowed, transposed output [n][m]) ----------------
__global__ void k_framesT(const float* __restrict__ x, const float* __restrict__ ref) {
    __shared__ float s[32][33];
    int tx = threadIdx.x, ty = threadIdx.y;   // block (32,8)
    int m0 = blockIdx.x * 32;
    int n0 = blockIdx.y * 32;
    int n = n0 + tx;
    float w = g_win[n];
    #pragma unroll
    for (int r4 = 0; r4 < 4; r4++) {
        int mr = ty + r4*8;
        int m = m0 + mr;
        float v = 0.0f;
        if (m < NFRF) {
            int ch = m / NT;
            int t  = m - ch*NT;
            const float* sig = (ch < 16) ? (x + ch*TLEN) : ref;
            int p = t*HOP + n - HOP;
            if (p >= 0 && p < TLEN) v = sig[p];
        }
        s[mr][tx] = v * w;
    }
    __syncthreads();
    int m = m0 + tx;
    if (m < NFRF) {
        #pragma unroll
        for (int r4 = 0; r4 < 4; r4++) {
            int nr = ty + r4*8;
            g_framesT[(n0 + nr)*NFRF + m] = s[tx][nr];
        }
    }
}

// ---------------- fwd stage 1 (radix-2 over n2):
// Z[r] = sum_{n2<10} (fr[n1+32n2] +/- fr[n1+32(n2+10)]) * e^{-2pi i r(n1+32n2)/640}
__global__ void __launch_bounds__(256) k_stage1() {
    __shared__ float  As[20][256];
    __shared__ float4 cts4[100];           // [n2<10][r-pair j<10]
    int m0 = blockIdx.x * 256;
    int n1 = blockIdx.y;
    int lid = threadIdx.x;

    #pragma unroll
    for (int i = 0; i < 20; i++) {
        int e = i*256 + lid;
        int n2 = e >> 8, ml = e & 255;
        int m = m0 + ml;
        As[n2][ml] = (m < NFRF) ? g_framesT[(n1 + 32*n2)*NFRF + m] : 0.0f;
    }
    if (lid < 100) cts4[lid] = ((const float4*)g_ct1)[n1*100 + lid];
    __syncthreads();

    float2 acc[20];
    #pragma unroll
    for (int r = 0; r < 20; r++) acc[r] = make_float2(0.f, 0.f);

    #pragma unroll
    for (int n2 = 0; n2 < 10; n2++) {
        float a = As[n2][lid];
        float b = As[n2 + 10][lid];
        float u = a + b;          // even r
        float v = a - b;          // odd r
        #pragma unroll
        for (int j = 0; j < 10; j++) {
            float4 c = cts4[n2*10 + j];
            acc[2*j  ].x += u*c.x;  acc[2*j  ].y += u*c.y;
            acc[2*j+1].x += v*c.z;  acc[2*j+1].y += v*c.w;
        }
    }

    int m = m0 + lid;
    if (m < NFRF) {
        #pragma unroll
        for (int r = 0; r < 20; r++)
            g_Z[(r*32 + n1)*NFRF + m] = acc[r];
    }
}

// ---------------- fwd stage 2 (radix-2 over n1):
// S[r+20q] = sum_{n1<16} (Z[n1] +/- Z[n1+16]) * e^{-2pi i q n1/32}
// dynamic smem: Zs[32][256] float2 (64KB) + twiddles
#define S2_SMEM (32*256*8 + 160*8 + 128*8)
__global__ void __launch_bounds__(256) k_stage2() {
    extern __shared__ float2 s2[];
    float2* Zs = s2;                     // [32][256]
    float2* Be = Zs + 32*256;            // [16][10]
    float2* Bo = Be + 160;               // [16][8]
    int m0 = blockIdx.x * 256;
    int r  = blockIdx.y;
    int lid = threadIdx.x;
    const float4* Be4 = (const float4*)Be;
    const float4* Bo4 = (const float4*)Bo;

    #pragma unroll
    for (int i = 0; i < 32; i++) {
        int m = m0 + lid;
        Zs[i*256 + lid] = (m < NFRF) ? g_Z[(r*32 + i)*NFRF + m] : make_float2(0.f, 0.f);
    }
    if (lid < 160) Be[lid] = g_W32e[lid];       // FIX: independent predicates,
    if (lid < 128) Bo[lid] = g_W32o[lid];       // Bo fully initialized
    __syncthreads();

    float2 acc[17];
    #pragma unroll
    for (int q = 0; q < 17; q++) acc[q] = make_float2(0.f, 0.f);

    #pragma unroll
    for (int n1 = 0; n1 < 16; n1++) {
        float2 za = Zs[n1*256 + lid];
        float2 zb = Zs[(n1 + 16)*256 + lid];
        float2 u = make_float2(za.x + zb.x, za.y + zb.y);   // even q
        float2 v = make_float2(za.x - zb.x, za.y - zb.y);   // odd q
        #pragma unroll
        for (int j = 0; j < 4; j++) {   // je = 2j, 2j+1 -> q = 4j, 4j+2
            float4 b = Be4[n1*5 + j];
            acc[4*j  ].x += u.x*b.x - u.y*b.y;
            acc[4*j  ].y += u.x*b.y + u.y*b.x;
            acc[4*j+2].x += u.x*b.z - u.y*b.w;
            acc[4*j+2].y += u.x*b.w + u.y*b.z;
        }
        {   // je = 8 -> q = 16
            float2 b = Be[n1*10 + 8];
            acc[16].x += u.x*b.x - u.y*b.y;
            acc[16].y += u.x*b.y + u.y*b.x;
        }
        #pragma unroll
        for (int j = 0; j < 4; j++) {   // jo = 2j, 2j+1 -> q = 4j+1, 4j+3
            float4 b = Bo4[n1*4 + j];
            acc[4*j+1].x += v.x*b.x - v.y*b.y;
            acc[4*j+1].y += v.x*b.y + v.y*b.x;
            acc[4*j+3].x += v.x*b.z - v.y*b.w;
            acc[4*j+3].y += v.x*b.w + v.y*b.z;
        }
    }

    int m = m0 + lid;
    if (m < NFRF) {
        #pragma unroll
        for (int q = 0; q < 17; q++) {
            int f = r + 20*q;
            if (f < NF) g_S[f*NFRF + m] = acc[q];
        }
    }
}

// ---------------- covariance features ----------------
__global__ void k_cov(float* __restrict__ out) {
    int idx = blockIdx.x*blockDim.x + threadIdx.x;
    if (idx >= 2*FT) return;
    int t = idx % NT;
    int f = (idx / NT) % NF;
    int b = idx / FT;
    float2 S[8];
    #pragma unroll
    for (int c = 0; c < 8; c++)
        S[c] = g_S[f*NFRF + (b*8 + c)*NT + t];
    float* o = out + OFF_FEATS + (b*74)*FT + f*NT + t;
    int p = 0;
    #pragma unroll
    for (int i = 0; i < 8; i++) {
        #pragma unroll
        for (int j = i; j < 8; j++) {
            float re = S[i].x*S[j].x + S[i].y*S[j].y;   // S_i * conj(S_j)
            float im = S[i].y*S[j].x - S[i].x*S[j].y;
            o[(2*p    )*FT] = re;
            o[(2*p + 1)*FT] = im;
            p++;
        }
    }
    o[72*FT] = S[3].x;
    o[73*FT] = S[3].y;
}

// ---------------- padded refS (b=0) ----------------
__global__ void k_refpad() {
    int idx = blockIdx.x*blockDim.x + threadIdx.x;
    if (idx >= 323*309) return;
    int fp = idx / 309, tp = idx - fp*309;
    int f = fp - 1, t = tp - 4;
    float2 v = make_float2(0.f, 0.f);
    if (f >= 0 && f < NF && t >= 0 && t < NT)
        v = g_S[f*NFRF + 16*NT + t];
    g_rp[idx] = v;
}

// ---------------- deep filtering (b=0 only), freq-major output ----------------
__global__ void k_deepfilter(const float2* __restrict__ rtf) {
    int idx = blockIdx.x*blockDim.x + threadIdx.x;
    if (idx >= 7*FT) return;
    int t = idx % NT;
    int f = (idx / NT) % NF;
    int m = idx / FT;
    const float2* rbase = rtf + m*27*FT + f*NT + t;  // b=0: [m][27][F][T] float2
    float2 acc = make_float2(0.f, 0.f);
    #pragma unroll
    for (int ki = 0; ki < 3; ki++) {
        #pragma unroll
        for (int kj = 0; kj < 9; kj++) {
            float2 r = rbase[(ki*9 + kj)*FT];
            float2 p = g_rp[(f + ki)*309 + (t + kj)];
            acc.x += r.x*p.x - r.y*p.y;
            acc.y += r.x*p.y + r.y*p.x;
        }
    }
    g_estF[f*MINV + m*NT + t] = acc;   // [k][R], R = m*NT + t
}

// ---------------- inv stage A: A1[r][n1][R] = sum_q ck*E[20q+r][R]*e^{+2pi i k n1/640}
// block 256 = 2 groups of 128; group g computes n1 in [16g, 16g+16)
__global__ void __launch_bounds__(256) k_istageA() {
    __shared__ float2 Es[17][128];
    __shared__ float2 TAs[17*32];
    int m0 = blockIdx.x * 128;
    int r  = blockIdx.y;
    int tid = threadIdx.x;
    int lid = tid & 127;
    int grp = tid >> 7;
    const float4* TAs4 = (const float4*)TAs;

    for (int e = tid; e < 544; e += 256) TAs[e] = g_TA[r*544 + e];
    for (int e = tid; e < 17*128; e += 256) {
        int q = e >> 7, ml = e & 127;
        int k = 20*q + r;
        int Rm = m0 + ml;
        Es[q][ml] = (k < NF && Rm < MINV) ? g_estF[k*MINV + Rm] : make_float2(0.f, 0.f);
    }
    __syncthreads();

    float2 acc[16];
    #pragma unroll
    for (int j = 0; j < 16; j++) acc[j] = make_float2(0.f, 0.f);

    #pragma unroll
    for (int q = 0; q < 17; q++) {
        float2 a = Es[q][lid];
        #pragma unroll
        for (int j = 0; j < 8; j++) {
            float4 t = TAs4[q*16 + grp*8 + j];
            acc[2*j  ].x += a.x*t.x - a.y*t.y;
            acc[2*j  ].y += a.x*t.y + a.y*t.x;
            acc[2*j+1].x += a.x*t.z - a.y*t.w;
            acc[2*j+1].y += a.x*t.w + a.y*t.z;
        }
    }

    int R = m0 + lid;
    int n1b = grp*16;
    if (R < MINV) {
        #pragma unroll
        for (int j = 0; j < 16; j++)
            g_A1[(r*32 + n1b + j)*MINV + R] = acc[j];
    }
}

// ---------------- inv stage B: y[R][n] = win[n]/640 * Re(sum_r A1[r][n1][R]*e^{+2pi i r n2/20})
__global__ void __launch_bounds__(256) k_istageB() {
    __shared__ float2 A1s[20][8][33];    // [r][mloc][n1] (pad to 33 for conflict-free)
    __shared__ float2 TBs[400];          // transposed [n2][r]
    __shared__ float  wins[NFFT];
    int R0 = blockIdx.x * 8;
    int lid = threadIdx.x;
    const float4* TBs4 = (const float4*)TBs;

    #pragma unroll
    for (int e = lid; e < 400; e += 256) TBs[e] = g_TBt[e];
    #pragma unroll
    for (int e = lid; e < NFFT; e += 256) wins[e] = g_win[e] * (1.0f/640.0f);
    #pragma unroll
    for (int i = 0; i < 20; i++) {
        int e = i*256 + lid;
        int rn1 = e >> 3, mloc = e & 7;
        int r = rn1 >> 5, n1 = rn1 & 31;
        int R = R0 + mloc;
        A1s[r][mloc][n1] = (R < MINV) ? g_A1[rn1*MINV + R] : make_float2(0.f, 0.f);
    }
    __syncthreads();

    #pragma unroll
    for (int mloc = 0; mloc < 8; mloc++) {
        int R = R0 + mloc;
        if (R >= MINV) break;    // uniform across block
        #pragma unroll
        for (int nb = 0; nb < 3; nb++) {
            int n = nb*256 + lid;
            if (n < NFFT) {
                int n1 = n & 31, n2 = n >> 5;
                float acc = 0.0f;
                #pragma unroll
                for (int jr = 0; jr < 10; jr++) {       // r = 2jr, 2jr+1
                    float4 t = TBs4[n2*10 + jr];
                    float2 a0 = A1s[2*jr  ][mloc][n1];
                    float2 a1 = A1s[2*jr+1][mloc][n1];
                    acc += a0.x*t.x - a0.y*t.y;
                    acc += a1.x*t.z - a1.y*t.w;
                }
                g_y[R*NFFT + n] = acc * wins[n];
            }
        }
    }
}

// ---------------- overlap-add + interleave output ----------------
__global__ void k_ola(const float* __restrict__ ref, float* __restrict__ out) {
    int s = blockIdx.x*blockDim.x + threadIdx.x;
    if (s >= TLEN) return;
    int sp = s + HOP;                 // position in uncropped signal
    int t1 = sp / HOP;                // in [1, 300]
    int n1 = sp - t1*HOP;             // [0, 320)
    int t0 = t1 - 1;
    int nn0 = n1 + HOP;               // [320, 640)
    float iw = g_invw[sp];
    float* o = out + s*8;
    #pragma unroll
    for (int m = 0; m < 7; m++) {
        float v = (g_y[(m*NT + t0)*NFFT + nn0] + g_y[(m*NT + t1)*NFFT + n1]) * iw;
        o[m < 3 ? m : m + 1] = v;
    }
    o[3] = ref[s];
}

// ---------------- launch ----------------
extern "C" void kernel_launch(void* const* d_in, const int* in_sizes, int n_in,
                              void* d_out, int out_size) {
    const float*  x   = (const float*)d_in[0];
    const float2* rtf = (const float2*)d_in[1];  // [B][7][3][9][F][T][2]; b=0 slice
    const float*  ref = (const float*)d_in[2];   // [2][1][T]; b=0 slice
    float* out = (float*)d_out;

    cudaFuncSetAttribute(k_stage2, cudaFuncAttributeMaxDynamicSharedMemorySize, S2_SMEM);

    k_tab<<<(TAB_END + 255)/256, 256>>>();
    {
        dim3 g((NFRF + 31)/32, NFFT/32);
        k_framesT<<<g, dim3(32, 8)>>>(x, ref);
    }
    {
        dim3 g((NFRF + 255)/256, 32);
        k_stage1<<<g, 256>>>();
    }
    {
        dim3 g((NFRF + 255)/256, 20);
        k_stage2<<<g, 256, S2_SMEM>>>();
    }
    k_cov<<<(2*FT + 255)/256, 256>>>(out);
    k_refpad<<<(323*309 + 255)/256, 256>>>();
    k_deepfilter<<<(7*FT + 255)/256, 256>>>(rtf);
    {
        dim3 g((MINV + 127)/128, 20);
        k_istageA<<<g, 256>>>();
    }
    {
        dim3 g((MINV + 7)/8);
        k_istageB<<<g, 256>>>();
    }
    k_ola<<<(TLEN + 255)/256, 256>>>(ref, out);
}

// round 14
// speedup vs baseline: 1.1629x; 1.0456x over previous
#include <cuda_runtime.h>

#define NFFT 640
#define HOP  320
#define NF   321            // freq bins
#define NT   301            // time frames
#define TLEN 96000
#define NCHF 17             // 16 x-channels + ref(b=0)
#define NFRF (NCHF*NT)      // 5117 forward frames
#define MINV (7*NT)         // 2107 inverse frames
#define LPAD 96640
#define FT   (NF*NT)        // 96621
#define OFF_FEATS 768000

#define TWO_PI 6.283185307179586f

// table segment offsets inside k_tab's index space (float2 units)
#define TAB_CT4  0                       // 3840 (32*5*24) fwd stage1 radix-4 (20 r's, 24 slots)
#define TAB_T4   3840                    // 144  (8*18)    fwd stage2 radix-4 (17 q's, 18 slots)
#define TAB_TA   3984                    // 10880 (20*17*32)
#define TAB_TB   14864                   // 400   (transposed [n2][r])
#define TAB_WIN  15264                   // 640
#define TAB_INVW 15904                   // LPAD
#define TAB_END  (TAB_INVW + LPAD)

// ---------------- scratch (device globals; no allocation allowed) -------------
__device__ float  g_win[NFFT];
__device__ float  g_invw[LPAD];
__device__ float4 g_ct4[32*5*12];      // stage1: [n1][j<5][12 float4 = 24 slots], residue-grouped r
__device__ float4 g_T4[72];            // stage2: [j<8][9 float4 = 18 slots], residue-grouped q
__device__ float2 g_TA[20*17*32];      // inv stageA: [r][q][n1] = ck*(cos,+sin)(2pi k n1/640), k=20q+r (0 if k>320)
__device__ float2 g_TBt[20*20];        // inv stageB TRANSPOSED: [n2][r] = (cos,+sin)(2pi r n2/20)
__device__ float  g_framesT[NFFT*NFRF];// transposed windowed frames [n][m]
__device__ float2 g_Z[640*NFRF];       // fwd stage1 output, [(r*32+n1)][m]
__device__ float2 g_S[NF*NFRF];        // STFT, freq-major [f][m], m = ch*NT + t
__device__ float2 g_rp[323*309];       // padded refS (b=0)
__device__ float2 g_estF[NF*MINV];     // est freq-major [k][R], R = m*NT + t
__device__ float2 g_A1[640*MINV];      // inv stageA output, [(r*32+n1)][R]
__device__ float  g_y[MINV*NFFT];      // inverse frames (pre-OLA, windowed)

__device__ __forceinline__ float hannf(int n) {
    return 0.5f - 0.5f*cosf(TWO_PI * (float)n / (float)NFFT);
}

// stage2 slot (0..17) -> q grouped by residue mod 4 (17 q's: 5/4/4/4); -1 = pad
__device__ __forceinline__ int slot2q(int slot) {
    if (slot < 5)  return 4*slot;            // q = 0,4,8,12,16
    if (slot == 5) return -1;                // pad
    if (slot < 10) return 4*(slot-6) + 1;    // q = 1,5,9,13
    if (slot < 14) return 4*(slot-10) + 2;   // q = 2,6,10,14
    return 4*(slot-14) + 3;                  // q = 3,7,11,15
}

// stage1 slot (0..23) -> r grouped by residue mod 4 (20 r's: 5/5/5/5); -1 = pad
__device__ __forceinline__ int slot2r(int slot) {
    int g = slot / 6, i = slot - 6*g;        // group g = residue, i in [0,6)
    return (i < 5) ? (4*i + g) : -1;
}

// ---------------- init: all twiddle tables + window + invw (one launch) -------
__global__ void k_tab() {
    int idx = blockIdx.x*blockDim.x + threadIdx.x;
    if (idx < TAB_T4) {
        // stage1 radix-4 combined twiddle: e^{-2pi i r (n1+32j)/640}, residue-grouped r
        int n1 = idx / 120;                  // 5*24 = 120 float2 per n1
        int rem = idx - n1*120;
        int j = rem / 24, slot = rem - j*24;
        int r = slot2r(slot);
        float2 v = make_float2(0.f, 0.f);
        if (r >= 0) {
            float s, c;
            sincosf(TWO_PI * (float)((r*(n1 + 32*j)) % NFFT) / (float)NFFT, &s, &c);
            v = make_float2(c, -s);
        }
        ((float2*)g_ct4)[idx] = v;
    } else if (idx < TAB_TA) {
        // stage2 radix-4 twiddle: e^{-2pi i q j/32}, j<8, residue-grouped q
        int e = idx - TAB_T4;
        int j = e / 18, slot = e - j*18;
        int q = slot2q(slot);
        float2 v = make_float2(0.f, 0.f);
        if (q >= 0) {
            float s, c;
            sincosf(TWO_PI * (float)((q*j) % 32) / 32.0f, &s, &c);
            v = make_float2(c, -s);
        }
        ((float2*)g_T4)[e] = v;
    } else if (idx < TAB_TB) {
        // inv stageA: ck * e^{+2pi i k n1/640}, k = 20q+r
        int e = idx - TAB_TA;
        int r = e / 544;
        int rem = e - r*544;
        int q = rem / 32, n1 = rem - q*32;
        int k = 20*q + r;
        float2 v = make_float2(0.f, 0.f);
        if (k <= 320) {
            float ck = (k == 0 || k == 320) ? 1.0f : 2.0f;
            float s, c;
            sincosf(TWO_PI * (float)((k*n1) % NFFT) / (float)NFFT, &s, &c);
            v = make_float2(ck*c, ck*s);
        }
        g_TA[e] = v;
    } else if (idx < TAB_WIN) {
        // inv stageB transposed: [n2][r] = e^{+2pi i r n2/20}
        int e = idx - TAB_TB;
        int n2 = e / 20, r = e - n2*20;
        float s, c;
        sincosf(TWO_PI * (float)((r*n2) % 20) / 20.0f, &s, &c);
        g_TBt[e] = make_float2(c, s);
    } else if (idx < TAB_INVW) {
        int n = idx - TAB_WIN;
        g_win[n] = hannf(n);
    } else if (idx < TAB_END) {
        // closed-form inverse window sum (periodic interior, short edges)
        int sp = idx - TAB_INVW;
        float wsum;
        if (sp < HOP) {
            float w = hannf(sp);
            wsum = w*w;
        } else if (sp < 96320) {
            int n1 = sp % HOP;
            float w0 = hannf(n1), w1 = hannf(n1 + HOP);
            wsum = w0*w0 + w1*w1;
        } else {
            float w = hannf(sp - 96000);
            wsum = w*w;
        }
        g_invw[sp] = (wsum > 1e-11f) ? (1.0f/wsum) : 1.0f;
    }
}

// ---------------- framing (windowed, transposed output [n][m]) ----------------
__global__ void k_framesT(const float* __restrict__ x, const float* __restrict__ ref) {
    __shared__ float s[32][33];
    int tx = threadIdx.x, ty = threadIdx.y;   // block (32,8)
    int m0 = blockIdx.x * 32;
    int n0 = blockIdx.y * 32;
    int n = n0 + tx;
    float w = g_win[n];
    #pragma unroll
    for (int r4 = 0; r4 < 4; r4++) {
        int mr = ty + r4*8;
        int m = m0 + mr;
        float v = 0.0f;
        if (m < NFRF) {
            int ch = m / NT;
            int t  = m - ch*NT;
            const float* sig = (ch < 16) ? (x + ch*TLEN) : ref;
            int p = t*HOP + n - HOP;
            if (p >= 0 && p < TLEN) v = sig[p];
        }
        s[mr][tx] = v * w;
    }
    __syncthreads();
    int m = m0 + tx;
    if (m < NFRF) {
        #pragma unroll
        for (int r4 = 0; r4 < 4; r4++) {
            int nr = ty + r4*8;
            g_framesT[(n0 + nr)*NFRF + m] = s[tx][nr];
        }
    }
}

// ---------------- fwd stage 1 (radix-4 over n2 = j + 5k):
// Z[r] = sum_j tw(r, n1+32j) * B_r(j),  B per r mod 4 from real butterflies
__global__ void __launch_bounds__(256) k_stage1() {
    __shared__ float  As[20][256];
    __shared__ float4 cts4s[60];           // [j<5][12 float4 = 24 slots]
    int m0 = blockIdx.x * 256;
    int n1 = blockIdx.y;
    int lid = threadIdx.x;

    #pragma unroll
    for (int i = 0; i < 20; i++) {
        int e = i*256 + lid;
        int n2 = e >> 8, ml = e & 255;
        int m = m0 + ml;
        As[n2][ml] = (m < NFRF) ? g_framesT[(n1 + 32*n2)*NFRF + m] : 0.0f;
    }
    if (lid < 60) cts4s[lid] = g_ct4[n1*60 + lid];
    __syncthreads();

    float2 acc[20];
    #pragma unroll
    for (int r = 0; r < 20; r++) acc[r] = make_float2(0.f, 0.f);

    #pragma unroll
    for (int j = 0; j < 5; j++) {
        float u0 = As[j     ][lid];
        float u1 = As[j + 5 ][lid];
        float u2 = As[j + 10][lid];
        float u3 = As[j + 15][lid];
        float s02 = u0 + u2, d02 = u0 - u2;
        float s13 = u1 + u3, d13 = u1 - u3;
        float A0 = s02 + s13, A2 = s02 - s13;
        int b4 = j*12;
        float4 t;
        // r ≡ 0 (real A0): r = 0,4 | 8,12 | 16
        t = cts4s[b4+0];
        acc[0].x  += A0*t.x; acc[0].y  += A0*t.y; acc[4].x  += A0*t.z; acc[4].y  += A0*t.w;
        t = cts4s[b4+1];
        acc[8].x  += A0*t.x; acc[8].y  += A0*t.y; acc[12].x += A0*t.z; acc[12].y += A0*t.w;
        t = cts4s[b4+2];
        acc[16].x += A0*t.x; acc[16].y += A0*t.y;
        // r ≡ 1: B = d02 - i d13:  re += d02*tx + d13*ty ; im += d02*ty - d13*tx
        t = cts4s[b4+3];
        acc[1].x  += d02*t.x + d13*t.y; acc[1].y  += d02*t.y - d13*t.x;
        acc[5].x  += d02*t.z + d13*t.w; acc[5].y  += d02*t.w - d13*t.z;
        t = cts4s[b4+4];
        acc[9].x  += d02*t.x + d13*t.y; acc[9].y  += d02*t.y - d13*t.x;
        acc[13].x += d02*t.z + d13*t.w; acc[13].y += d02*t.w - d13*t.z;
        t = cts4s[b4+5];
        acc[17].x += d02*t.x + d13*t.y; acc[17].y += d02*t.y - d13*t.x;
        // r ≡ 2 (real A2): r = 2,6 | 10,14 | 18
        t = cts4s[b4+6];
        acc[2].x  += A2*t.x; acc[2].y  += A2*t.y; acc[6].x  += A2*t.z; acc[6].y  += A2*t.w;
        t = cts4s[b4+7];
        acc[10].x += A2*t.x; acc[10].y += A2*t.y; acc[14].x += A2*t.z; acc[14].y += A2*t.w;
        t = cts4s[b4+8];
        acc[18].x += A2*t.x; acc[18].y += A2*t.y;
        // r ≡ 3: B = d02 + i d13:  re += d02*tx - d13*ty ; im += d02*ty + d13*tx
        t = cts4s[b4+9];
        acc[3].x  += d02*t.x - d13*t.y; acc[3].y  += d02*t.y + d13*t.x;
        acc[7].x  += d02*t.z - d13*t.w; acc[7].y  += d02*t.w + d13*t.z;
        t = cts4s[b4+10];
        acc[11].x += d02*t.x - d13*t.y; acc[11].y += d02*t.y + d13*t.x;
        acc[15].x += d02*t.z - d13*t.w; acc[15].y += d02*t.w + d13*t.z;
        t = cts4s[b4+11];
        acc[19].x += d02*t.x - d13*t.y; acc[19].y += d02*t.y + d13*t.x;
    }

    int m = m0 + lid;
    if (m < NFRF) {
        #pragma unroll
        for (int r = 0; r < 20; r++)
            g_Z[(r*32 + n1)*NFRF + m] = acc[r];
    }
}

// complex MAC: a += z * (tx + i ty)
#define CMAC(a, z, tx, ty) do { \
    (a).x += (z).x*(tx) - (z).y*(ty); \
    (a).y += (z).x*(ty) + (z).y*(tx); } while (0)

// ---------------- fwd stage 2 (radix-4 over n1 = j + 8k):
// S[r+20q] = sum_{j<8} tw(q,j) * B_q(j),  B per q mod 4 from complex butterflies
__global__ void __launch_bounds__(128) k_stage2() {
    __shared__ float2 Zs[32][128];
    __shared__ float4 T4s[72];             // [j<8][9 float4 = 18 slots]
    int m0 = blockIdx.x * 128;
    int r  = blockIdx.y;
    int lid = threadIdx.x;

    int m = m0 + lid;
    #pragma unroll
    for (int i = 0; i < 32; i++)
        Zs[i][lid] = (m < NFRF) ? g_Z[(r*32 + i)*NFRF + m] : make_float2(0.f, 0.f);
    if (lid < 72) T4s[lid] = g_T4[lid];
    __syncthreads();

    float2 acc[17];
    #pragma unroll
    for (int q = 0; q < 17; q++) acc[q] = make_float2(0.f, 0.f);

    #pragma unroll
    for (int j = 0; j < 8; j++) {
        float2 za = Zs[j     ][lid];
        float2 zb = Zs[j + 8 ][lid];
        float2 zc = Zs[j + 16][lid];
        float2 zd = Zs[j + 24][lid];
        float2 s02 = make_float2(za.x + zc.x, za.y + zc.y);
        float2 d02 = make_float2(za.x - zc.x, za.y - zc.y);
        float2 s13 = make_float2(zb.x + zd.x, zb.y + zd.y);
        float2 d13 = make_float2(zb.x - zd.x, zb.y - zd.y);
        float2 A0 = make_float2(s02.x + s13.x, s02.y + s13.y);
        float2 A2 = make_float2(s02.x - s13.x, s02.y - s13.y);
        float2 A1 = make_float2(d02.x + d13.y, d02.y - d13.x);   // d02 - i d13
        float2 A3 = make_float2(d02.x - d13.y, d02.y + d13.x);   // d02 + i d13
        int b4 = j*9;
        float4 t;
        t = T4s[b4+0];  CMAC(acc[0],  A0, t.x, t.y);  CMAC(acc[4],  A0, t.z, t.w);
        t = T4s[b4+1];  CMAC(acc[8],  A0, t.x, t.y);  CMAC(acc[12], A0, t.z, t.w);
        t = T4s[b4+2];  CMAC(acc[16], A0, t.x, t.y);
        t = T4s[b4+3];  CMAC(acc[1],  A1, t.x, t.y);  CMAC(acc[5],  A1, t.z, t.w);
        t = T4s[b4+4];  CMAC(acc[9],  A1, t.x, t.y);  CMAC(acc[13], A1, t.z, t.w);
        t = T4s[b4+5];  CMAC(acc[2],  A2, t.x, t.y);  CMAC(acc[6],  A2, t.z, t.w);
        t = T4s[b4+6];  CMAC(acc[10], A2, t.x, t.y);  CMAC(acc[14], A2, t.z, t.w);
        t = T4s[b4+7];  CMAC(acc[3],  A3, t.x, t.y);  CMAC(acc[7],  A3, t.z, t.w);
        t = T4s[b4+8];  CMAC(acc[11], A3, t.x, t.y);  CMAC(acc[15], A3, t.z, t.w);
    }

    if (m < NFRF) {
        #pragma unroll
        for (int q = 0; q < 17; q++) {
            int f = r + 20*q;
            if (f < NF) g_S[f*NFRF + m] = acc[q];
        }
    }
}

// ---------------- covariance features ----------------
__global__ void k_cov(float* __restrict__ out) {
    int idx = blockIdx.x*blockDim.x + threadIdx.x;
    if (idx >= 2*FT) return;
    int t = idx % NT;
    int f = (idx / NT) % NF;
    int b = idx / FT;
    float2 S[8];
    #pragma unroll
    for (int c = 0; c < 8; c++)
        S[c] = g_S[f*NFRF + (b*8 + c)*NT + t];
    float* o = out + OFF_FEATS + (b*74)*FT + f*NT + t;
    int p = 0;
    #pragma unroll
    for (int i = 0; i < 8; i++) {
        #pragma unroll
        for (int j = i; j < 8; j++) {
            float re = S[i].x*S[j].x + S[i].y*S[j].y;   // S_i * conj(S_j)
            float im = S[i].y*S[j].x - S[i].x*S[j].y;
            o[(2*p    )*FT] = re;
            o[(2*p + 1)*FT] = im;
            p++;
        }
    }
    o[72*FT] = S[3].x;
    o[73*FT] = S[3].y;
}

// ---------------- padded refS (b=0) ----------------
__global__ void k_refpad() {
    int idx = blockIdx.x*blockDim.x + threadIdx.x;
    if (idx >= 323*309) return;
    int fp = idx / 309, tp = idx - fp*309;
    int f = fp - 1, t = tp - 4;
    float2 v = make_float2(0.f, 0.f);
    if (f >= 0 && f < NF && t >= 0 && t < NT)
        v = g_S[f*NFRF + 16*NT + t];
    g_rp[idx] = v;
}

// ---------------- deep filtering (b=0 only), freq-major output ----------------
__global__ void k_deepfilter(const float2* __restrict__ rtf) {
    int idx = blockIdx.x*blockDim.x + threadIdx.x;
    if (idx >= 7*FT) return;
    int t = idx % NT;
    int f = (idx / NT) % NF;
    int m = idx / FT;
    const float2* rbase = rtf + m*27*FT + f*NT + t;  // b=0: [m][27][F][T] float2
    float2 acc = make_float2(0.f, 0.f);
    #pragma unroll
    for (int ki = 0; ki < 3; ki++) {
        #pragma unroll
        for (int kj = 0; kj < 9; kj++) {
            float2 r = rbase[(ki*9 + kj)*FT];
            float2 p = g_rp[(f + ki)*309 + (t + kj)];
            acc.x += r.x*p.x - r.y*p.y;
            acc.y += r.x*p.y + r.y*p.x;
        }
    }
    g_estF[f*MINV + m*NT + t] = acc;   // [k][R], R = m*NT + t
}

// ---------------- inv stage A: A1[r][n1][R] = sum_q ck*E[20q+r][R]*e^{+2pi i k n1/640}
// block 256 = 2 groups of 128; group g computes n1 in [16g, 16g+16)
__global__ void __launch_bounds__(256) k_istageA() {
    __shared__ float2 Es[17][128];
    __shared__ float2 TAs[17*32];
    int m0 = blockIdx.x * 128;
    int r  = blockIdx.y;
    int tid = threadIdx.x;
    int lid = tid & 127;
    int grp = tid >> 7;
    const float4* TAs4 = (const float4*)TAs;

    for (int e = tid; e < 544; e += 256) TAs[e] = g_TA[r*544 + e];
    for (int e = tid; e < 17*128; e += 256) {
        int q = e >> 7, ml = e & 127;
        int k = 20*q + r;
        int Rm = m0 + ml;
        Es[q][ml] = (k < NF && Rm < MINV) ? g_estF[k*MINV + Rm] : make_float2(0.f, 0.f);
    }
    __syncthreads();

    float2 acc[16];
    #pragma unroll
    for (int j = 0; j < 16; j++) acc[j] = make_float2(0.f, 0.f);

    #pragma unroll
    for (int q = 0; q < 17; q++) {
        float2 a = Es[q][lid];
        #pragma unroll
        for (int j = 0; j < 8; j++) {
            float4 t = TAs4[q*16 + grp*8 + j];
            acc[2*j  ].x += a.x*t.x - a.y*t.y;
            acc[2*j  ].y += a.x*t.y + a.y*t.x;
            acc[2*j+1].x += a.x*t.z - a.y*t.w;
            acc[2*j+1].y += a.x*t.w + a.y*t.z;
        }
    }

    int R = m0 + lid;
    int n1b = grp*16;
    if (R < MINV) {
        #pragma unroll
        for (int j = 0; j < 16; j++)
            g_A1[(r*32 + n1b + j)*MINV + R] = acc[j];
    }
}

// ---------------- inv stage B: y[R][n] = win[n]/640 * Re(sum_r A1[r][n1][R]*e^{+2pi i r n2/20})
__global__ void __launch_bounds__(256) k_istageB() {
    __shared__ float2 A1s[20][8][33];    // [r][mloc][n1] (pad to 33 for conflict-free)
    __shared__ float2 TBs[400];          // transposed [n2][r]
    __shared__ float  wins[NFFT];
    int R0 = blockIdx.x * 8;
    int lid = threadIdx.x;
    const float4* TBs4 = (const float4*)TBs;

    #pragma unroll
    for (int e = lid; e < 400; e += 256) TBs[e] = g_TBt[e];
    #pragma unroll
    for (int e = lid; e < NFFT; e += 256) wins[e] = g_win[e] * (1.0f/640.0f);
    #pragma unroll
    for (int i = 0; i < 20; i++) {
        int e = i*256 + lid;
        int rn1 = e >> 3, mloc = e & 7;
        int r = rn1 >> 5, n1 = rn1 & 31;
        int R = R0 + mloc;
        A1s[r][mloc][n1] = (R < MINV) ? g_A1[rn1*MINV + R] : make_float2(0.f, 0.f);
    }
    __syncthreads();

    #pragma unroll
    for (int mloc = 0; mloc < 8; mloc++) {
        int R = R0 + mloc;
        if (R >= MINV) break;    // uniform across block
        #pragma unroll
        for (int nb = 0; nb < 3; nb++) {
            int n = nb*256 + lid;
            if (n < NFFT) {
                int n1 = n & 31, n2 = n >> 5;
                float acc = 0.0f;
                #pragma unroll
                for (int jr = 0; jr < 10; jr++) {       // r = 2jr, 2jr+1
                    float4 t = TBs4[n2*10 + jr];
                    float2 a0 = A1s[2*jr  ][mloc][n1];
                    float2 a1 = A1s[2*jr+1][mloc][n1];
                    acc += a0.x*t.x - a0.y*t.y;
                    acc += a1.x*t.z - a1.y*t.w;
                }
                g_y[R*NFFT + n] = acc * wins[n];
            }
        }
    }
}

// ---------------- overlap-add + interleave output ----------------
__global__ void k_ola(const float* __restrict__ ref, float* __restrict__ out) {
    int s = blockIdx.x*blockDim.x + threadIdx.x;
    if (s >= TLEN) return;
    int sp = s + HOP;                 // position in uncropped signal
    int t1 = sp / HOP;                // in [1, 300]
    int n1 = sp - t1*HOP;             // [0, 320)
    int t0 = t1 - 1;
    int nn0 = n1 + HOP;               // [320, 640)
    float iw = g_invw[sp];
    float* o = out + s*8;
    #pragma unroll
    for (int m = 0; m < 7; m++) {
        float v = (g_y[(m*NT + t0)*NFFT + nn0] + g_y[(m*NT + t1)*NFFT + n1]) * iw;
        o[m < 3 ? m : m + 1] = v;
    }
    o[3] = ref[s];
}

// ---------------- launch ----------------
extern "C" void kernel_launch(void* const* d_in, const int* in_sizes, int n_in,
                              void* d_out, int out_size) {
    const float*  x   = (const float*)d_in[0];
    const float2* rtf = (const float2*)d_in[1];  // [B][7][3][9][F][T][2]; b=0 slice
    const float*  ref = (const float*)d_in[2];   // [2][1][T]; b=0 slice
    float* out = (float*)d_out;

    k_tab<<<(TAB_END + 255)/256, 256>>>();
    {
        dim3 g((NFRF + 31)/32, NFFT/32);
        k_framesT<<<g, dim3(32, 8)>>>(x, ref);
    }
    {
        dim3 g((NFRF + 255)/256, 32);
        k_stage1<<<g, 256>>>();
    }
    {
        dim3 g((NFRF + 127)/128, 20);
        k_stage2<<<g, 128>>>();
    }
    k_cov<<<(2*FT + 255)/256, 256>>>(out);
    k_refpad<<<(323*309 + 255)/256, 256>>>();
    k_deepfilter<<<(7*FT + 255)/256, 256>>>(rtf);
    {
        dim3 g((MINV + 127)/128, 20);
        k_istageA<<<g, 256>>>();
    }
    {
        dim3 g((MINV + 7)/8);
        k_istageB<<<g, 256>>>();
    }
    k_ola<<<(TLEN + 255)/256, 256>>>(ref, out);
}

// round 15
// speedup vs baseline: 1.1843x; 1.0184x over previous
#include <cuda_runtime.h>

#define NFFT 640
#define HOP  320
#define NF   321            // freq bins
#define NT   301            // time frames
#define TLEN 96000
#define NCHF 17             // 16 x-channels + ref(b=0)
#define NFRF (NCHF*NT)      // 5117 forward frames
#define MINV (7*NT)         // 2107 inverse frames
#define LPAD 96640
#define FT   (NF*NT)        // 96621
#define OFF_FEATS 768000

#define TWO_PI 6.283185307179586f

// table segment offsets inside k_tab's index space (float2 units)
#define TAB_CT4  0                       // 3840 (32*5*24) fwd stage1 radix-4 (20 r's, 24 slots)
#define TAB_T4   3840                    // 144  (8*18)    fwd stage2 radix-4 (17 q's, 18 slots)
#define TAB_TA   3984                    // 10880 (20*17*32)
#define TAB_TB   14864                   // 400   (transposed [n2][r])
#define TAB_WIN  15264                   // 640
#define TAB_INVW 15904                   // LPAD
#define TAB_END  (TAB_INVW + LPAD)

// ---------------- scratch (device globals; no allocation allowed) -------------
__device__ float  g_win[NFFT];
__device__ float  g_invw[LPAD];
__device__ float4 g_ct4[32*5*12];      // stage1: [n1][j<5][12 float4 = 24 slots], residue-grouped r
__device__ float4 g_T4[72];            // stage2: [j<8][9 float4 = 18 slots], residue-grouped q
__device__ float2 g_TA[20*17*32];      // inv stageA: [r][q][n1] = ck*(cos,+sin)(2pi k n1/640), k=20q+r (0 if k>320)
__device__ float2 g_TBt[20*20];        // inv stageB TRANSPOSED: [n2][r] = (cos,+sin)(2pi r n2/20)
__device__ float  g_framesT[NFFT*NFRF];// transposed windowed frames [n][m]
__device__ float2 g_Z[640*NFRF];       // fwd stage1 output, [(r*32+n1)][m]
__device__ float2 g_S[NF*NFRF];        // STFT, freq-major [f][m], m = ch*NT + t
__device__ float2 g_rp[323*309];       // padded refS (b=0)
__device__ float2 g_estF[NF*MINV];     // est freq-major [k][R], R = m*NT + t
__device__ float2 g_A1[640*MINV];      // inv stageA output, [(r*32+n1)][R]
__device__ float  g_y[MINV*NFFT];      // inverse frames (pre-OLA, windowed)

__device__ __forceinline__ float hannf(int n) {
    return 0.5f - 0.5f*cosf(TWO_PI * (float)n / (float)NFFT);
}

// stage2 slot (0..17) -> q grouped by residue mod 4 (17 q's: 5/4/4/4); -1 = pad
__device__ __forceinline__ int slot2q(int slot) {
    if (slot < 5)  return 4*slot;            // q = 0,4,8,12,16
    if (slot == 5) return -1;                // pad
    if (slot < 10) return 4*(slot-6) + 1;    // q = 1,5,9,13
    if (slot < 14) return 4*(slot-10) + 2;   // q = 2,6,10,14
    return 4*(slot-14) + 3;                  // q = 3,7,11,15
}

// stage1 slot (0..23) -> r grouped by residue mod 4 (20 r's: 5/5/5/5); -1 = pad
__device__ __forceinline__ int slot2r(int slot) {
    int g = slot / 6, i = slot - 6*g;        // group g = residue, i in [0,6)
    return (i < 5) ? (4*i + g) : -1;
}

// ---------------- init: all twiddle tables + window + invw (one launch) -------
__global__ void k_tab() {
    int idx = blockIdx.x*blockDim.x + threadIdx.x;
    if (idx < TAB_T4) {
        // stage1 radix-4 combined twiddle: e^{-2pi i r (n1+32j)/640}, residue-grouped r
        int n1 = idx / 120;                  // 5*24 = 120 float2 per n1
        int rem = idx - n1*120;
        int j = rem / 24, slot = rem - j*24;
        int r = slot2r(slot);
        float2 v = make_float2(0.f, 0.f);
        if (r >= 0) {
            float s, c;
            sincosf(TWO_PI * (float)((r*(n1 + 32*j)) % NFFT) / (float)NFFT, &s, &c);
            v = make_float2(c, -s);
        }
        ((float2*)g_ct4)[idx] = v;
    } else if (idx < TAB_TA) {
        // stage2 radix-4 twiddle: e^{-2pi i q j/32}, j<8, residue-grouped q
        int e = idx - TAB_T4;
        int j = e / 18, slot = e - j*18;
        int q = slot2q(slot);
        float2 v = make_float2(0.f, 0.f);
        if (q >= 0) {
            float s, c;
            sincosf(TWO_PI * (float)((q*j) % 32) / 32.0f, &s, &c);
            v = make_float2(c, -s);
        }
        ((float2*)g_T4)[e] = v;
    } else if (idx < TAB_TB) {
        // inv stageA: ck * e^{+2pi i k n1/640}, k = 20q+r
        int e = idx - TAB_TA;
        int r = e / 544;
        int rem = e - r*544;
        int q = rem / 32, n1 = rem - q*32;
        int k = 20*q + r;
        float2 v = make_float2(0.f, 0.f);
        if (k <= 320) {
            float ck = (k == 0 || k == 320) ? 1.0f : 2.0f;
            float s, c;
            sincosf(TWO_PI * (float)((k*n1) % NFFT) / (float)NFFT, &s, &c);
            v = make_float2(ck*c, ck*s);
        }
        g_TA[e] = v;
    } else if (idx < TAB_WIN) {
        // inv stageB transposed: [n2][r] = e^{+2pi i r n2/20}
        int e = idx - TAB_TB;
        int n2 = e / 20, r = e - n2*20;
        float s, c;
        sincosf(TWO_PI * (float)((r*n2) % 20) / 20.0f, &s, &c);
        g_TBt[e] = make_float2(c, s);
    } else if (idx < TAB_INVW) {
        int n = idx - TAB_WIN;
        g_win[n] = hannf(n);
    } else if (idx < TAB_END) {
        // closed-form inverse window sum (periodic interior, short edges)
        int sp = idx - TAB_INVW;
        float wsum;
        if (sp < HOP) {
            float w = hannf(sp);
            wsum = w*w;
        } else if (sp < 96320) {
            int n1 = sp % HOP;
            float w0 = hannf(n1), w1 = hannf(n1 + HOP);
            wsum = w0*w0 + w1*w1;
        } else {
            float w = hannf(sp - 96000);
            wsum = w*w;
        }
        g_invw[sp] = (wsum > 1e-11f) ? (1.0f/wsum) : 1.0f;
    }
}

// ---------------- framing (windowed, transposed output [n][m]) ----------------
__global__ void k_framesT(const float* __restrict__ x, const float* __restrict__ ref) {
    __shared__ float s[32][33];
    int tx = threadIdx.x, ty = threadIdx.y;   // block (32,8)
    int m0 = blockIdx.x * 32;
    int n0 = blockIdx.y * 32;
    int n = n0 + tx;
    float w = g_win[n];
    #pragma unroll
    for (int r4 = 0; r4 < 4; r4++) {
        int mr = ty + r4*8;
        int m = m0 + mr;
        float v = 0.0f;
        if (m < NFRF) {
            int ch = m / NT;
            int t  = m - ch*NT;
            const float* sig = (ch < 16) ? (x + ch*TLEN) : ref;
            int p = t*HOP + n - HOP;
            if (p >= 0 && p < TLEN) v = sig[p];
        }
        s[mr][tx] = v * w;
    }
    __syncthreads();
    int m = m0 + tx;
    if (m < NFRF) {
        #pragma unroll
        for (int r4 = 0; r4 < 4; r4++) {
            int nr = ty + r4*8;
            g_framesT[(n0 + nr)*NFRF + m] = s[tx][nr];
        }
    }
}

// ---------------- fwd stage 1 (radix-4 over n2 = j + 5k):
// Z[r] = sum_j tw(r, n1+32j) * B_r(j),  B per r mod 4 from real butterflies
__global__ void __launch_bounds__(256) k_stage1() {
    __shared__ float  As[20][256];
    __shared__ float4 cts4s[60];           // [j<5][12 float4 = 24 slots]
    int m0 = blockIdx.x * 256;
    int n1 = blockIdx.y;
    int lid = threadIdx.x;

    #pragma unroll
    for (int i = 0; i < 20; i++) {
        int e = i*256 + lid;
        int n2 = e >> 8, ml = e & 255;
        int m = m0 + ml;
        As[n2][ml] = (m < NFRF) ? g_framesT[(n1 + 32*n2)*NFRF + m] : 0.0f;
    }
    if (lid < 60) cts4s[lid] = g_ct4[n1*60 + lid];
    __syncthreads();

    float2 acc[20];
    #pragma unroll
    for (int r = 0; r < 20; r++) acc[r] = make_float2(0.f, 0.f);

    #pragma unroll
    for (int j = 0; j < 5; j++) {
        float u0 = As[j     ][lid];
        float u1 = As[j + 5 ][lid];
        float u2 = As[j + 10][lid];
        float u3 = As[j + 15][lid];
        float s02 = u0 + u2, d02 = u0 - u2;
        float s13 = u1 + u3, d13 = u1 - u3;
        float A0 = s02 + s13, A2 = s02 - s13;
        int b4 = j*12;
        float4 t;
        // r ≡ 0 (real A0): r = 0,4 | 8,12 | 16
        t = cts4s[b4+0];
        acc[0].x  += A0*t.x; acc[0].y  += A0*t.y; acc[4].x  += A0*t.z; acc[4].y  += A0*t.w;
        t = cts4s[b4+1];
        acc[8].x  += A0*t.x; acc[8].y  += A0*t.y; acc[12].x += A0*t.z; acc[12].y += A0*t.w;
        t = cts4s[b4+2];
        acc[16].x += A0*t.x; acc[16].y += A0*t.y;
        // r ≡ 1: B = d02 - i d13:  re += d02*tx + d13*ty ; im += d02*ty - d13*tx
        t = cts4s[b4+3];
        acc[1].x  += d02*t.x + d13*t.y; acc[1].y  += d02*t.y - d13*t.x;
        acc[5].x  += d02*t.z + d13*t.w; acc[5].y  += d02*t.w - d13*t.z;
        t = cts4s[b4+4];
        acc[9].x  += d02*t.x + d13*t.y; acc[9].y  += d02*t.y - d13*t.x;
        acc[13].x += d02*t.z + d13*t.w; acc[13].y += d02*t.w - d13*t.z;
        t = cts4s[b4+5];
        acc[17].x += d02*t.x + d13*t.y; acc[17].y += d02*t.y - d13*t.x;
        // r ≡ 2 (real A2): r = 2,6 | 10,14 | 18
        t = cts4s[b4+6];
        acc[2].x  += A2*t.x; acc[2].y  += A2*t.y; acc[6].x  += A2*t.z; acc[6].y  += A2*t.w;
        t = cts4s[b4+7];
        acc[10].x += A2*t.x; acc[10].y += A2*t.y; acc[14].x += A2*t.z; acc[14].y += A2*t.w;
        t = cts4s[b4+8];
        acc[18].x += A2*t.x; acc[18].y += A2*t.y;
        // r ≡ 3: B = d02 + i d13:  re += d02*tx - d13*ty ; im += d02*ty + d13*tx
        t = cts4s[b4+9];
        acc[3].x  += d02*t.x - d13*t.y; acc[3].y  += d02*t.y + d13*t.x;
        acc[7].x  += d02*t.z - d13*t.w; acc[7].y  += d02*t.w + d13*t.z;
        t = cts4s[b4+10];
        acc[11].x += d02*t.x - d13*t.y; acc[11].y += d02*t.y + d13*t.x;
        acc[15].x += d02*t.z - d13*t.w; acc[15].y += d02*t.w + d13*t.z;
        t = cts4s[b4+11];
        acc[19].x += d02*t.x - d13*t.y; acc[19].y += d02*t.y + d13*t.x;
    }

    int m = m0 + lid;
    if (m < NFRF) {
        #pragma unroll
        for (int r = 0; r < 20; r++)
            g_Z[(r*32 + n1)*NFRF + m] = acc[r];
    }
}

// complex MAC: a += z * (tx + i ty)
#define CMAC(a, z, tx, ty) do { \
    (a).x += (z).x*(tx) - (z).y*(ty); \
    (a).y += (z).x*(ty) + (z).y*(tx); } while (0)

// ---------------- fwd stage 2 (radix-4 over n1 = j + 8k):
// S[r+20q] = sum_{j<8} tw(q,j) * B_q(j),  B per q mod 4 from complex butterflies
__global__ void __launch_bounds__(128) k_stage2() {
    __shared__ float2 Zs[32][128];
    __shared__ float4 T4s[72];             // [j<8][9 float4 = 18 slots]
    int m0 = blockIdx.x * 128;
    int r  = blockIdx.y;
    int lid = threadIdx.x;

    int m = m0 + lid;
    #pragma unroll
    for (int i = 0; i < 32; i++)
        Zs[i][lid] = (m < NFRF) ? g_Z[(r*32 + i)*NFRF + m] : make_float2(0.f, 0.f);
    if (lid < 72) T4s[lid] = g_T4[lid];
    __syncthreads();

    float2 acc[17];
    #pragma unroll
    for (int q = 0; q < 17; q++) acc[q] = make_float2(0.f, 0.f);

    #pragma unroll
    for (int j = 0; j < 8; j++) {
        float2 za = Zs[j     ][lid];
        float2 zb = Zs[j + 8 ][lid];
        float2 zc = Zs[j + 16][lid];
        float2 zd = Zs[j + 24][lid];
        float2 s02 = make_float2(za.x + zc.x, za.y + zc.y);
        float2 d02 = make_float2(za.x - zc.x, za.y - zc.y);
        float2 s13 = make_float2(zb.x + zd.x, zb.y + zd.y);
        float2 d13 = make_float2(zb.x - zd.x, zb.y - zd.y);
        float2 A0 = make_float2(s02.x + s13.x, s02.y + s13.y);
        float2 A2 = make_float2(s02.x - s13.x, s02.y - s13.y);
        float2 A1 = make_float2(d02.x + d13.y, d02.y - d13.x);   // d02 - i d13
        float2 A3 = make_float2(d02.x - d13.y, d02.y + d13.x);   // d02 + i d13
        int b4 = j*9;
        float4 t;
        t = T4s[b4+0];  CMAC(acc[0],  A0, t.x, t.y);  CMAC(acc[4],  A0, t.z, t.w);
        t = T4s[b4+1];  CMAC(acc[8],  A0, t.x, t.y);  CMAC(acc[12], A0, t.z, t.w);
        t = T4s[b4+2];  CMAC(acc[16], A0, t.x, t.y);
        t = T4s[b4+3];  CMAC(acc[1],  A1, t.x, t.y);  CMAC(acc[5],  A1, t.z, t.w);
        t = T4s[b4+4];  CMAC(acc[9],  A1, t.x, t.y);  CMAC(acc[13], A1, t.z, t.w);
        t = T4s[b4+5];  CMAC(acc[2],  A2, t.x, t.y);  CMAC(acc[6],  A2, t.z, t.w);
        t = T4s[b4+6];  CMAC(acc[10], A2, t.x, t.y);  CMAC(acc[14], A2, t.z, t.w);
        t = T4s[b4+7];  CMAC(acc[3],  A3, t.x, t.y);  CMAC(acc[7],  A3, t.z, t.w);
        t = T4s[b4+8];  CMAC(acc[11], A3, t.x, t.y);  CMAC(acc[15], A3, t.z, t.w);
    }

    if (m < NFRF) {
        #pragma unroll
        for (int q = 0; q < 17; q++) {
            int f = r + 20*q;
            if (f < NF) g_S[f*NFRF + m] = acc[q];
        }
    }
}

// ---------------- covariance features ----------------
__global__ void k_cov(float* __restrict__ out) {
    int idx = blockIdx.x*blockDim.x + threadIdx.x;
    if (idx >= 2*FT) return;
    int t = idx % NT;
    int f = (idx / NT) % NF;
    int b = idx / FT;
    float2 S[8];
    #pragma unroll
    for (int c = 0; c < 8; c++)
        S[c] = g_S[f*NFRF + (b*8 + c)*NT + t];
    float* o = out + OFF_FEATS + (b*74)*FT + f*NT + t;
    int p = 0;
    #pragma unroll
    for (int i = 0; i < 8; i++) {
        #pragma unroll
        for (int j = i; j < 8; j++) {
            float re = S[i].x*S[j].x + S[i].y*S[j].y;   // S_i * conj(S_j)
            float im = S[i].y*S[j].x - S[i].x*S[j].y;
            o[(2*p    )*FT] = re;
            o[(2*p + 1)*FT] = im;
            p++;
        }
    }
    o[72*FT] = S[3].x;
    o[73*FT] = S[3].y;
}

// ---------------- padded refS (b=0) ----------------
__global__ void k_refpad() {
    int idx = blockIdx.x*blockDim.x + threadIdx.x;
    if (idx >= 323*309) return;
    int fp = idx / 309, tp = idx - fp*309;
    int f = fp - 1, t = tp - 4;
    float2 v = make_float2(0.f, 0.f);
    if (f >= 0 && f < NF && t >= 0 && t < NT)
        v = g_S[f*NFRF + 16*NT + t];
    g_rp[idx] = v;
}

// ---------------- deep filtering (b=0 only), freq-major output ----------------
__global__ void k_deepfilter(const float2* __restrict__ rtf) {
    int idx = blockIdx.x*blockDim.x + threadIdx.x;
    if (idx >= 7*FT) return;
    int t = idx % NT;
    int f = (idx / NT) % NF;
    int m = idx / FT;
    const float2* rbase = rtf + m*27*FT + f*NT + t;  // b=0: [m][27][F][T] float2
    float2 acc = make_float2(0.f, 0.f);
    #pragma unroll
    for (int ki = 0; ki < 3; ki++) {
        #pragma unroll
        for (int kj = 0; kj < 9; kj++) {
            float2 r = rbase[(ki*9 + kj)*FT];
            float2 p = g_rp[(f + ki)*309 + (t + kj)];
            acc.x += r.x*p.x - r.y*p.y;
            acc.y += r.x*p.y + r.y*p.x;
        }
    }
    g_estF[f*MINV + m*NT + t] = acc;   // [k][R], R = m*NT + t
}

// ---------------- inv stage A: A1[r][n1][R] = sum_q ck*E[20q+r][R]*e^{+2pi i k n1/640}
// block 256 = 2 groups of 128; group g computes n1 in [16g, 16g+16)
__global__ void __launch_bounds__(256) k_istageA() {
    __shared__ float2 Es[17][128];
    __shared__ float2 TAs[17*32];
    int m0 = blockIdx.x * 128;
    int r  = blockIdx.y;
    int tid = threadIdx.x;
    int lid = tid & 127;
    int grp = tid >> 7;
    const float4* TAs4 = (const float4*)TAs;

    for (int e = tid; e < 544; e += 256) TAs[e] = g_TA[r*544 + e];
    for (int e = tid; e < 17*128; e += 256) {
        int q = e >> 7, ml = e & 127;
        int k = 20*q + r;
        int Rm = m0 + ml;
        Es[q][ml] = (k < NF && Rm < MINV) ? g_estF[k*MINV + Rm] : make_float2(0.f, 0.f);
    }
    __syncthreads();

    float2 acc[16];
    #pragma unroll
    for (int j = 0; j < 16; j++) acc[j] = make_float2(0.f, 0.f);

    #pragma unroll
    for (int q = 0; q < 17; q++) {
        float2 a = Es[q][lid];
        #pragma unroll
        for (int j = 0; j < 8; j++) {
            float4 t = TAs4[q*16 + grp*8 + j];
            acc[2*j  ].x += a.x*t.x - a.y*t.y;
            acc[2*j  ].y += a.x*t.y + a.y*t.x;
            acc[2*j+1].x += a.x*t.z - a.y*t.w;
            acc[2*j+1].y += a.x*t.w + a.y*t.z;
        }
    }

    int R = m0 + lid;
    int n1b = grp*16;
    if (R < MINV) {
        #pragma unroll
        for (int j = 0; j < 16; j++)
            g_A1[(r*32 + n1b + j)*MINV + R] = acc[j];
    }
}

// ---------------- inv stage B: y[R][n] = win[n]/640 * Re(sum_r A1[r][n1][R]*e^{+2pi i r n2/20})
__global__ void __launch_bounds__(256) k_istageB() {
    __shared__ float2 A1s[20][8][33];    // [r][mloc][n1] (pad to 33 for conflict-free)
    __shared__ float2 TBs[400];          // transposed [n2][r]
    __shared__ float  wins[NFFT];
    int R0 = blockIdx.x * 8;
    int lid = threadIdx.x;
    const float4* TBs4 = (const float4*)TBs;

    #pragma unroll
    for (int e = lid; e < 400; e += 256) TBs[e] = g_TBt[e];
    #pragma unroll
    for (int e = lid; e < NFFT; e += 256) wins[e] = g_win[e] * (1.0f/640.0f);
    #pragma unroll
    for (int i = 0; i < 20; i++) {
        int e = i*256 + lid;
        int rn1 = e >> 3, mloc = e & 7;
        int r = rn1 >> 5, n1 = rn1 & 31;
        int R = R0 + mloc;
        A1s[r][mloc][n1] = (R < MINV) ? g_A1[rn1*MINV + R] : make_float2(0.f, 0.f);
    }
    __syncthreads();

    #pragma unroll
    for (int mloc = 0; mloc < 8; mloc++) {
        int R = R0 + mloc;
        if (R >= MINV) break;    // uniform across block
        #pragma unroll
        for (int nb = 0; nb < 3; nb++) {
            int n = nb*256 + lid;
            if (n < NFFT) {
                int n1 = n & 31, n2 = n >> 5;
                float acc = 0.0f;
                #pragma unroll
                for (int jr = 0; jr < 10; jr++) {       // r = 2jr, 2jr+1
                    float4 t = TBs4[n2*10 + jr];
                    float2 a0 = A1s[2*jr  ][mloc][n1];
                    float2 a1 = A1s[2*jr+1][mloc][n1];
                    acc += a0.x*t.x - a0.y*t.y;
                    acc += a1.x*t.z - a1.y*t.w;
                }
                g_y[R*NFFT + n] = acc * wins[n];
            }
        }
    }
}

// ---------------- overlap-add + interleave output ----------------
__global__ void k_ola(const float* __restrict__ ref, float* __restrict__ out) {
    int s = blockIdx.x*blockDim.x + threadIdx.x;
    if (s >= TLEN) return;
    int sp = s + HOP;                 // position in uncropped signal
    int t1 = sp / HOP;                // in [1, 300]
    int n1 = sp - t1*HOP;             // [0, 320)
    int t0 = t1 - 1;
    int nn0 = n1 + HOP;               // [320, 640)
    float iw = g_invw[sp];
    float* o = out + s*8;
    #pragma unroll
    for (int m = 0; m < 7; m++) {
        float v = (g_y[(m*NT + t0)*NFFT + nn0] + g_y[(m*NT + t1)*NFFT + n1]) * iw;
        o[m < 3 ? m : m + 1] = v;
    }
    o[3] = ref[s];
}

// ---------------- launch (forked stream: cov overlaps the deepfilter chain) ---
extern "C" void kernel_launch(void* const* d_in, const int* in_sizes, int n_in,
                              void* d_out, int out_size) {
    const float*  x   = (const float*)d_in[0];
    const float2* rtf = (const float2*)d_in[1];  // [B][7][3][9][F][T][2]; b=0 slice
    const float*  ref = (const float*)d_in[2];   // [2][1][T]; b=0 slice
    float* out = (float*)d_out;

    cudaStream_t s2;
    cudaEvent_t evS, evC;
    cudaStreamCreateWithFlags(&s2, cudaStreamNonBlocking);
    cudaEventCreateWithFlags(&evS, cudaEventDisableTiming);
    cudaEventCreateWithFlags(&evC, cudaEventDisableTiming);

    k_tab<<<(TAB_END + 255)/256, 256>>>();
    {
        dim3 g((NFRF + 31)/32, NFFT/32);
        k_framesT<<<g, dim3(32, 8)>>>(x, ref);
    }
    {
        dim3 g((NFRF + 255)/256, 32);
        k_stage1<<<g, 256>>>();
    }
    {
        dim3 g((NFRF + 127)/128, 20);
        k_stage2<<<g, 128>>>();
    }

    // fork: cov on side stream, deepfilter chain on main stream
    cudaEventRecord(evS, 0);
    cudaStreamWaitEvent(s2, evS, 0);
    k_cov<<<(2*FT + 255)/256, 256, 0, s2>>>(out);
    cudaEventRecord(evC, s2);

    k_refpad<<<(323*309 + 255)/256, 256>>>();
    k_deepfilter<<<(7*FT + 255)/256, 256>>>(rtf);
    {
        dim3 g((MINV + 127)/128, 20);
        k_istageA<<<g, 256>>>();
    }
    {
        dim3 g((MINV + 7)/8);
        k_istageB<<<g, 256>>>();
    }
    k_ola<<<(TLEN + 255)/256, 256>>>(ref, out);

    // join: main stream completes only after cov
    cudaStreamWaitEvent(0, evC, 0);
}